// round 15
// baseline (speedup 1.0000x reference)
#include <cuda_runtime.h>
#include <cuda_fp16.h>
#include <cstdint>

#define IN_F   4096
#define OUT_F  11008
#define M_MAX  8192
#define NGROUPS (OUT_F * (IN_F / 16))   // 2818048
#define DEQ_BLOCKS (NGROUPS / 256)      // 11008
#define CONV_BLOCKS ((M_MAX * IN_F / 8) / 256)   // 16384

// ---------------- scratch (static device arrays) ----------------
__device__ __align__(1024) __half g_wh[(size_t)OUT_F * IN_F];  // dequantized W, fp16
__device__ __align__(1024) __half g_xh[(size_t)M_MAX * IN_F];  // X, fp16

__device__ __forceinline__ uint32_t h2u(__half2 h) {
    union { __half2 h; uint32_t u; } c;
    c.h = h;
    return c.u;
}

// ---------------- kernel 1: merged pre-pass (dequant W + convert X) ----------
__global__ void prep_kernel(const int* __restrict__ Q, const float* __restrict__ NORM,
                            const float4* __restrict__ X) {
    int b = blockIdx.x;
    if (b < DEQ_BLOCKS) {
        size_t g = (size_t)b * 256 + threadIdx.x;
        const int4* qp = reinterpret_cast<const int4*>(Q + g * 8);
        int4 q0 = qp[0];
        int4 q1 = qp[1];
        float n = NORM[g];
        float s = n * (2.0f / 7.0f);
        int v[8] = {q0.x, q0.y, q0.z, q0.w, q1.x, q1.y, q1.z, q1.w};
        uint32_t h[8];
#pragma unroll
        for (int i = 0; i < 8; i++) {
            float w0 = fmaf((float)(v[i] & 7), s, -n);
            float w1 = fmaf((float)((v[i] >> 3) & 7), s, -n);
            h[i] = h2u(__floats2half2_rn(w0, w1));
        }
        uint4* dst = reinterpret_cast<uint4*>(g_wh + g * 16);
        uint4 o0, o1;
        o0.x = h[0]; o0.y = h[1]; o0.z = h[2]; o0.w = h[3];
        o1.x = h[4]; o1.y = h[5]; o1.z = h[6]; o1.w = h[7];
        dst[0] = o0;
        dst[1] = o1;
    } else {
        size_t i = (size_t)(b - DEQ_BLOCKS) * 256 + threadIdx.x;  // 8 floats each
        float4 v0 = X[2 * i];
        float4 v1 = X[2 * i + 1];
        uint4 o;
        o.x = h2u(__floats2half2_rn(v0.x, v0.y));
        o.y = h2u(__floats2half2_rn(v0.z, v0.w));
        o.z = h2u(__floats2half2_rn(v1.x, v1.y));
        o.w = h2u(__floats2half2_rn(v1.z, v1.w));
        reinterpret_cast<uint4*>(g_xh)[i] = o;
    }
}

// ---------------- kernel 2: pipelined fp16 mma GEMM, 2 CTAs/SM --------------
// CTA tile 128(M) x 128(N) x 64(K halves), 256 threads = 8 warps in 2(M) x 4(N),
// warp tile 64 x 32. 3 stages x 32 KB = 96 KB/CTA, single __syncthreads/iter.
// r15 = r14 + critical-path reorder: bf LDSMs before af; LD_FRAGS(0) before
// the producer cp.asyncs so MMAs start one LDSM-chain earlier per iteration.
#define BM 128
#define BN 128
#define BKH 64
#define ROWW 32
#define STAGES 3
#define A_WORDS (BM * ROWW)                      // 4096
#define B_WORDS (BN * ROWW)                      // 4096
#define STAGE_WORDS (A_WORDS + B_WORDS)          // 8192 words = 32 KB
#define SMEM_BYTES (STAGES * STAGE_WORDS * 4)    // 96 KB
#define NKT (IN_F / BKH)                          // 64
#define NTH 256

__device__ __forceinline__ void cp16(uint32_t dst, const void* src) {
    asm volatile("cp.async.cg.shared.global [%0], [%1], 16;" :: "r"(dst), "l"(src));
}

__device__ __forceinline__ void ldsm4(uint32_t* r, uint32_t addr) {
    asm volatile("ldmatrix.sync.aligned.m8n8.x4.shared.b16 {%0,%1,%2,%3}, [%4];"
        : "=r"(r[0]), "=r"(r[1]), "=r"(r[2]), "=r"(r[3]) : "r"(addr));
}

__device__ __forceinline__ void mma_f16(float* d, const uint32_t* a, const uint32_t* b) {
    asm volatile(
        "mma.sync.aligned.m16n8k16.row.col.f32.f16.f16.f32 "
        "{%0,%1,%2,%3}, {%4,%5,%6,%7}, {%8,%9}, {%0,%1,%2,%3};"
        : "+f"(d[0]), "+f"(d[1]), "+f"(d[2]), "+f"(d[3])
        : "r"(a[0]), "r"(a[1]), "r"(a[2]), "r"(a[3]),
          "r"(b[0]), "r"(b[1]));
}

__global__ __launch_bounds__(NTH, 2)
void gemm_mma_f16(const __half* __restrict__ A,     // g_xh [M, K]
                  const __half* __restrict__ B,     // g_wh [N, K]
                  const float* __restrict__ bias,
                  float* __restrict__ C,
                  int mtiles)
{
    extern __shared__ __align__(1024) uint32_t smw[];
    const int tid  = threadIdx.x;
    const int lane = tid & 31;
    const int warp = tid >> 5;
    const int wm   = warp & 1;          // M dir: 64 rows each
    const int wn   = warp >> 1;         // N dir: 32 cols each

    // ---- grouped rasterization (GM=8) ----
    const int NT = OUT_F / BN;          // 86
    const int GM = 8;
    int bid   = blockIdx.x;
    int grp   = bid / (GM * NT);
    int first = grp * GM;
    int gsz   = (mtiles - first < GM) ? (mtiles - first) : GM;
    int rem   = bid - grp * GM * NT;
    int mt    = first + rem % gsz;
    int nt    = rem / gsz;
    const int m0 = mt * BM;
    const int n0 = nt * BN;

    const __half* gA = A + (size_t)m0 * IN_F;
    const __half* gB = B + (size_t)n0 * IN_F;

    const int lrow = tid >> 3;          // 0..31
    const int lkc  = tid & 7;
    const uint32_t s_base = (uint32_t)__cvta_generic_to_shared(smw);

    // ---- ldmatrix per-lane address components (derivation verified r7/r8) ----
    const int p  = lane >> 3;           // matrix part 0..3
    const int rl = lane & 7;            // row within 8-row matrix
    const int a_cbit = p >> 1;
    const int a_roff = rl + (p & 1) * 8;
    const int b_cbit = p & 1;
    const int b_roff = rl + (p >> 1) * 8;

    uint32_t a_rowb[4], b_rowb[2];
#pragma unroll
    for (int mi = 0; mi < 4; mi++) a_rowb[mi] = (uint32_t)(wm * 64 + mi * 16 + a_roff) * 128;
#pragma unroll
    for (int nj = 0; nj < 2; nj++) b_rowb[nj] = (uint32_t)(wn * 32 + nj * 16 + b_roff) * 128;

    // precomputed swizzle offsets per ks (loop-invariant)
    uint32_t aswk[4], bswk[4];
#pragma unroll
    for (int ks = 0; ks < 4; ks++) {
        aswk[ks] = (uint32_t)(((2 * ks + a_cbit) ^ rl) << 4);
        bswk[ks] = (uint32_t)(((2 * ks + b_cbit) ^ rl) << 4);
    }

    float acc[4][4][4];
#pragma unroll
    for (int mi = 0; mi < 4; mi++)
#pragma unroll
        for (int ni = 0; ni < 4; ni++)
#pragma unroll
            for (int q = 0; q < 4; q++) acc[mi][ni][q] = 0.0f;

#define LOAD_TILE(stg, kt) do {                                                   \
    uint32_t sa = s_base + (uint32_t)((stg) * STAGE_WORDS) * 4;                   \
    uint32_t sb = sa + A_WORDS * 4;                                               \
    _Pragma("unroll")                                                             \
    for (int i = 0; i < 4; i++) {                                                 \
        int row = lrow + i * 32;                                                  \
        uint32_t schunk = (uint32_t)(lkc ^ (row & 7));                            \
        cp16(sa + (uint32_t)(row * ROWW + schunk * 4) * 4,                        \
             gA + (size_t)row * IN_F + (kt) * BKH + lkc * 8);                     \
    }                                                                             \
    _Pragma("unroll")                                                             \
    for (int i = 0; i < 4; i++) {                                                 \
        int row = lrow + i * 32;                                                  \
        uint32_t schunk = (uint32_t)(lkc ^ (row & 7));                            \
        cp16(sb + (uint32_t)(row * ROWW + schunk * 4) * 4,                        \
             gB + (size_t)row * IN_F + (kt) * BKH + lkc * 8);                     \
    }                                                                             \
    asm volatile("cp.async.commit_group;");                                       \
} while (0)

    uint32_t af[4][4], bf[2][4];

    // B first: the first MMA (mi=0) depends on bf + af[0]; make those the
    // earliest LDSMs so af[1..3] latency hides behind the first MMAs.
#define LD_FRAGS(ks, sAb, sBb) do {                                               \
    _Pragma("unroll")                                                             \
    for (int nj = 0; nj < 2; nj++) ldsm4(bf[nj], (sBb) + b_rowb[nj] + bswk[ks]);  \
    _Pragma("unroll")                                                             \
    for (int mi = 0; mi < 4; mi++) ldsm4(af[mi], (sAb) + a_rowb[mi] + aswk[ks]);  \
} while (0)

    // prologue: stages 0..1
#pragma unroll
    for (int s = 0; s < STAGES - 1; s++) LOAD_TILE(s, s);

#pragma unroll 3
    for (int t = 0; t < NKT; t++) {
        asm volatile("cp.async.wait_group %0;" :: "n"(STAGES - 2));
        __syncthreads();   // single barrier per iter (stage rewritten was read last iter)

        const uint32_t sAb = s_base + (uint32_t)((t % STAGES) * STAGE_WORDS) * 4;
        const uint32_t sBb = sAb + A_WORDS * 4;

        // fragments for ks=0 first (shortest path to the first MMA), then the
        // producer cp.asyncs ride the MMA shadow.
        LD_FRAGS(0, sAb, sBb);

        int nxt = t + STAGES - 1;
        if (nxt < NKT) {
            LOAD_TILE(nxt % STAGES, nxt);
        } else {
            asm volatile("cp.async.commit_group;");
        }

#pragma unroll
        for (int ks = 0; ks < 4; ks++) {
            if (ks > 0) LD_FRAGS(ks, sAb, sBb);
#pragma unroll
            for (int mi = 0; mi < 4; mi++)
#pragma unroll
                for (int ni = 0; ni < 4; ni++)
                    mma_f16(acc[mi][ni], af[mi], &bf[ni >> 1][(ni & 1) * 2]);
        }
    }

    // ---- epilogue: bias + store ----
    const int g = lane >> 2;
    const int tig = lane & 3;
#pragma unroll
    for (int mi = 0; mi < 4; mi++) {
        const int row = m0 + wm * 64 + mi * 16 + g;
        float* c0 = C + (size_t)row * OUT_F;
        float* c1 = C + (size_t)(row + 8) * OUT_F;
#pragma unroll
        for (int ni = 0; ni < 4; ni++) {
            const int col = n0 + wn * 32 + ni * 8 + tig * 2;
            float2 bv = *reinterpret_cast<const float2*>(bias + col);
            float2 o0, o1;
            o0.x = acc[mi][ni][0] + bv.x;
            o0.y = acc[mi][ni][1] + bv.y;
            o1.x = acc[mi][ni][2] + bv.x;
            o1.y = acc[mi][ni][3] + bv.y;
            *reinterpret_cast<float2*>(c0 + col) = o0;
            *reinterpret_cast<float2*>(c1 + col) = o1;
        }
    }
}

// ---------------- host launcher ----------------
extern "C" void kernel_launch(void* const* d_in, const int* in_sizes, int n_in,
                              void* d_out, int out_size)
{
    const float* x    = (const float*)d_in[0];
    const int*   q3   = (const int*)  d_in[1];
    const float* nrm  = (const float*)d_in[2];
    const float* bias = (const float*)d_in[3];
    float* out = (float*)d_out;

    const int M = in_sizes[0] / IN_F;            // 8192

    void* wptr = nullptr; cudaGetSymbolAddress(&wptr, g_wh);
    void* xptr = nullptr; cudaGetSymbolAddress(&xptr, g_xh);

    prep_kernel<<<DEQ_BLOCKS + CONV_BLOCKS, 256>>>(
        q3, nrm, reinterpret_cast<const float4*>(x));

    cudaFuncSetAttribute(gemm_mma_f16,
                         cudaFuncAttributeMaxDynamicSharedMemorySize, SMEM_BYTES);
    const int mtiles = M / BM;                   // 64
    const int grid = mtiles * (OUT_F / BN);      // 64 * 86 = 5504
    gemm_mma_f16<<<grid, NTH, SMEM_BYTES>>>((const __half*)xptr, (const __half*)wptr,
                                            bias, out, mtiles);
}

// round 16
// speedup vs baseline: 1.0225x; 1.0225x over previous
#include <cuda_runtime.h>
#include <cuda_fp16.h>
#include <cstdint>

#define IN_F   4096
#define OUT_F  11008
#define M_MAX  8192
#define NGROUPS (OUT_F * (IN_F / 16))   // 2818048
#define DEQ_BLOCKS (NGROUPS / 256)      // 11008
#define CONV_BLOCKS ((M_MAX * IN_F / 8) / 256)   // 16384

// ---------------- scratch (static device arrays) ----------------
__device__ __align__(1024) __half g_wh[(size_t)OUT_F * IN_F];  // dequantized W, fp16
__device__ __align__(1024) __half g_xh[(size_t)M_MAX * IN_F];  // X, fp16

__device__ __forceinline__ uint32_t h2u(__half2 h) {
    union { __half2 h; uint32_t u; } c;
    c.h = h;
    return c.u;
}

// ---------------- kernel 1: merged pre-pass (dequant W + convert X) ----------
__global__ void prep_kernel(const int* __restrict__ Q, const float* __restrict__ NORM,
                            const float4* __restrict__ X) {
    int b = blockIdx.x;
    if (b < DEQ_BLOCKS) {
        size_t g = (size_t)b * 256 + threadIdx.x;
        const int4* qp = reinterpret_cast<const int4*>(Q + g * 8);
        int4 q0 = qp[0];
        int4 q1 = qp[1];
        float n = NORM[g];
        float s = n * (2.0f / 7.0f);
        int v[8] = {q0.x, q0.y, q0.z, q0.w, q1.x, q1.y, q1.z, q1.w};
        uint32_t h[8];
#pragma unroll
        for (int i = 0; i < 8; i++) {
            float w0 = fmaf((float)(v[i] & 7), s, -n);
            float w1 = fmaf((float)((v[i] >> 3) & 7), s, -n);
            h[i] = h2u(__floats2half2_rn(w0, w1));
        }
        uint4* dst = reinterpret_cast<uint4*>(g_wh + g * 16);
        uint4 o0, o1;
        o0.x = h[0]; o0.y = h[1]; o0.z = h[2]; o0.w = h[3];
        o1.x = h[4]; o1.y = h[5]; o1.z = h[6]; o1.w = h[7];
        dst[0] = o0;
        dst[1] = o1;
    } else {
        size_t i = (size_t)(b - DEQ_BLOCKS) * 256 + threadIdx.x;  // 8 floats each
        float4 v0 = X[2 * i];
        float4 v1 = X[2 * i + 1];
        uint4 o;
        o.x = h2u(__floats2half2_rn(v0.x, v0.y));
        o.y = h2u(__floats2half2_rn(v0.z, v0.w));
        o.z = h2u(__floats2half2_rn(v1.x, v1.y));
        o.w = h2u(__floats2half2_rn(v1.z, v1.w));
        reinterpret_cast<uint4*>(g_xh)[i] = o;
    }
}

// ---------------- kernel 2: pipelined fp16 mma GEMM, 2 CTAs/SM --------------
// CTA tile 128(M) x 128(N) x 64(K halves), 256 threads = 8 warps in 2(M) x 4(N),
// warp tile 64 x 32. 3 stages x 32 KB = 96 KB/CTA, single __syncthreads/iter.
// Final config (= r14): unroll-3 mainloop (compile-time stage offsets) +
// precomputed swizzle offsets (no per-iter address ALU). Best: 1616.6 us.
#define BM 128
#define BN 128
#define BKH 64
#define ROWW 32
#define STAGES 3
#define A_WORDS (BM * ROWW)                      // 4096
#define B_WORDS (BN * ROWW)                      // 4096
#define STAGE_WORDS (A_WORDS + B_WORDS)          // 8192 words = 32 KB
#define SMEM_BYTES (STAGES * STAGE_WORDS * 4)    // 96 KB
#define NKT (IN_F / BKH)                          // 64
#define NTH 256

__device__ __forceinline__ void cp16(uint32_t dst, const void* src) {
    asm volatile("cp.async.cg.shared.global [%0], [%1], 16;" :: "r"(dst), "l"(src));
}

__device__ __forceinline__ void ldsm4(uint32_t* r, uint32_t addr) {
    asm volatile("ldmatrix.sync.aligned.m8n8.x4.shared.b16 {%0,%1,%2,%3}, [%4];"
        : "=r"(r[0]), "=r"(r[1]), "=r"(r[2]), "=r"(r[3]) : "r"(addr));
}

__device__ __forceinline__ void mma_f16(float* d, const uint32_t* a, const uint32_t* b) {
    asm volatile(
        "mma.sync.aligned.m16n8k16.row.col.f32.f16.f16.f32 "
        "{%0,%1,%2,%3}, {%4,%5,%6,%7}, {%8,%9}, {%0,%1,%2,%3};"
        : "+f"(d[0]), "+f"(d[1]), "+f"(d[2]), "+f"(d[3])
        : "r"(a[0]), "r"(a[1]), "r"(a[2]), "r"(a[3]),
          "r"(b[0]), "r"(b[1]));
}

__global__ __launch_bounds__(NTH, 2)
void gemm_mma_f16(const __half* __restrict__ A,     // g_xh [M, K]
                  const __half* __restrict__ B,     // g_wh [N, K]
                  const float* __restrict__ bias,
                  float* __restrict__ C,
                  int mtiles)
{
    extern __shared__ __align__(1024) uint32_t smw[];
    const int tid  = threadIdx.x;
    const int lane = tid & 31;
    const int warp = tid >> 5;
    const int wm   = warp & 1;          // M dir: 64 rows each
    const int wn   = warp >> 1;         // N dir: 32 cols each

    // ---- grouped rasterization (GM=8) ----
    const int NT = OUT_F / BN;          // 86
    const int GM = 8;
    int bid   = blockIdx.x;
    int grp   = bid / (GM * NT);
    int first = grp * GM;
    int gsz   = (mtiles - first < GM) ? (mtiles - first) : GM;
    int rem   = bid - grp * GM * NT;
    int mt    = first + rem % gsz;
    int nt    = rem / gsz;
    const int m0 = mt * BM;
    const int n0 = nt * BN;

    const __half* gA = A + (size_t)m0 * IN_F;
    const __half* gB = B + (size_t)n0 * IN_F;

    const int lrow = tid >> 3;          // 0..31
    const int lkc  = tid & 7;
    const uint32_t s_base = (uint32_t)__cvta_generic_to_shared(smw);

    // ---- ldmatrix per-lane address components (derivation verified r7/r8) ----
    const int p  = lane >> 3;           // matrix part 0..3
    const int rl = lane & 7;            // row within 8-row matrix
    const int a_cbit = p >> 1;
    const int a_roff = rl + (p & 1) * 8;
    const int b_cbit = p & 1;
    const int b_roff = rl + (p >> 1) * 8;

    uint32_t a_rowb[4], b_rowb[2];
#pragma unroll
    for (int mi = 0; mi < 4; mi++) a_rowb[mi] = (uint32_t)(wm * 64 + mi * 16 + a_roff) * 128;
#pragma unroll
    for (int nj = 0; nj < 2; nj++) b_rowb[nj] = (uint32_t)(wn * 32 + nj * 16 + b_roff) * 128;

    // precomputed swizzle offsets per ks (loop-invariant)
    uint32_t aswk[4], bswk[4];
#pragma unroll
    for (int ks = 0; ks < 4; ks++) {
        aswk[ks] = (uint32_t)(((2 * ks + a_cbit) ^ rl) << 4);
        bswk[ks] = (uint32_t)(((2 * ks + b_cbit) ^ rl) << 4);
    }

    float acc[4][4][4];
#pragma unroll
    for (int mi = 0; mi < 4; mi++)
#pragma unroll
        for (int ni = 0; ni < 4; ni++)
#pragma unroll
            for (int q = 0; q < 4; q++) acc[mi][ni][q] = 0.0f;

#define LOAD_TILE(stg, kt) do {                                                   \
    uint32_t sa = s_base + (uint32_t)((stg) * STAGE_WORDS) * 4;                   \
    uint32_t sb = sa + A_WORDS * 4;                                               \
    _Pragma("unroll")                                                             \
    for (int i = 0; i < 4; i++) {                                                 \
        int row = lrow + i * 32;                                                  \
        uint32_t schunk = (uint32_t)(lkc ^ (row & 7));                            \
        cp16(sa + (uint32_t)(row * ROWW + schunk * 4) * 4,                        \
             gA + (size_t)row * IN_F + (kt) * BKH + lkc * 8);                     \
    }                                                                             \
    _Pragma("unroll")                                                             \
    for (int i = 0; i < 4; i++) {                                                 \
        int row = lrow + i * 32;                                                  \
        uint32_t schunk = (uint32_t)(lkc ^ (row & 7));                            \
        cp16(sb + (uint32_t)(row * ROWW + schunk * 4) * 4,                        \
             gB + (size_t)row * IN_F + (kt) * BKH + lkc * 8);                     \
    }                                                                             \
    asm volatile("cp.async.commit_group;");                                       \
} while (0)

    uint32_t af[4][4], bf[2][4];

#define LD_FRAGS(ks, sAb, sBb) do {                                               \
    _Pragma("unroll")                                                             \
    for (int mi = 0; mi < 4; mi++) ldsm4(af[mi], (sAb) + a_rowb[mi] + aswk[ks]);  \
    _Pragma("unroll")                                                             \
    for (int nj = 0; nj < 2; nj++) ldsm4(bf[nj], (sBb) + b_rowb[nj] + bswk[ks]);  \
} while (0)

    // prologue: stages 0..1
#pragma unroll
    for (int s = 0; s < STAGES - 1; s++) LOAD_TILE(s, s);

#pragma unroll 3
    for (int t = 0; t < NKT; t++) {
        asm volatile("cp.async.wait_group %0;" :: "n"(STAGES - 2));
        __syncthreads();   // single barrier per iter (stage rewritten was read last iter)

        const uint32_t sAb = s_base + (uint32_t)((t % STAGES) * STAGE_WORDS) * 4;
        const uint32_t sBb = sAb + A_WORDS * 4;

        int nxt = t + STAGES - 1;
        if (nxt < NKT) {
            LOAD_TILE(nxt % STAGES, nxt);
        } else {
            asm volatile("cp.async.commit_group;");
        }

#pragma unroll
        for (int ks = 0; ks < 4; ks++) {
            LD_FRAGS(ks, sAb, sBb);
#pragma unroll
            for (int mi = 0; mi < 4; mi++)
#pragma unroll
                for (int ni = 0; ni < 4; ni++)
                    mma_f16(acc[mi][ni], af[mi], &bf[ni >> 1][(ni & 1) * 2]);
        }
    }

    // ---- epilogue: bias + store ----
    const int g = lane >> 2;
    const int tig = lane & 3;
#pragma unroll
    for (int mi = 0; mi < 4; mi++) {
        const int row = m0 + wm * 64 + mi * 16 + g;
        float* c0 = C + (size_t)row * OUT_F;
        float* c1 = C + (size_t)(row + 8) * OUT_F;
#pragma unroll
        for (int ni = 0; ni < 4; ni++) {
            const int col = n0 + wn * 32 + ni * 8 + tig * 2;
            float2 bv = *reinterpret_cast<const float2*>(bias + col);
            float2 o0, o1;
            o0.x = acc[mi][ni][0] + bv.x;
            o0.y = acc[mi][ni][1] + bv.y;
            o1.x = acc[mi][ni][2] + bv.x;
            o1.y = acc[mi][ni][3] + bv.y;
            *reinterpret_cast<float2*>(c0 + col) = o0;
            *reinterpret_cast<float2*>(c1 + col) = o1;
        }
    }
}

// ---------------- host launcher ----------------
extern "C" void kernel_launch(void* const* d_in, const int* in_sizes, int n_in,
                              void* d_out, int out_size)
{
    const float* x    = (const float*)d_in[0];
    const int*   q3   = (const int*)  d_in[1];
    const float* nrm  = (const float*)d_in[2];
    const float* bias = (const float*)d_in[3];
    float* out = (float*)d_out;

    const int M = in_sizes[0] / IN_F;            // 8192

    void* wptr = nullptr; cudaGetSymbolAddress(&wptr, g_wh);
    void* xptr = nullptr; cudaGetSymbolAddress(&xptr, g_xh);

    prep_kernel<<<DEQ_BLOCKS + CONV_BLOCKS, 256>>>(
        q3, nrm, reinterpret_cast<const float4*>(x));

    cudaFuncSetAttribute(gemm_mma_f16,
                         cudaFuncAttributeMaxDynamicSharedMemorySize, SMEM_BYTES);
    const int mtiles = M / BM;                   // 64
    const int grid = mtiles * (OUT_F / BN);      // 64 * 86 = 5504
    gemm_mma_f16<<<grid, NTH, SMEM_BYTES>>>((const __half*)xptr, (const __half*)wptr,
                                            bias, out, mtiles);
}

// round 17
// speedup vs baseline: 1.1146x; 1.0901x over previous
#include <cuda_runtime.h>
#include <cuda.h>
#include <cuda_fp16.h>
#include <cstdint>

#define IN_F   4096
#define OUT_F  11008
#define M_MAX  8192
#define NGROUPS (OUT_F * (IN_F / 16))   // 2818048
#define DEQ_BLOCKS (NGROUPS / 256)      // 11008
#define CONV_BLOCKS ((M_MAX * IN_F / 8) / 256)   // 16384

// ---------------- scratch (static device arrays) ----------------
__device__ __align__(1024) __half g_wh[(size_t)OUT_F * IN_F];  // dequantized W, fp16
__device__ __align__(1024) __half g_xh[(size_t)M_MAX * IN_F];  // X, fp16

__device__ __forceinline__ uint32_t h2u(__half2 h) {
    union { __half2 h; uint32_t u; } c;
    c.h = h;
    return c.u;
}

// ---------------- kernel 1: merged pre-pass (dequant W + convert X) ----------
__global__ void prep_kernel(const int* __restrict__ Q, const float* __restrict__ NORM,
                            const float4* __restrict__ X) {
    int b = blockIdx.x;
    if (b < DEQ_BLOCKS) {
        size_t g = (size_t)b * 256 + threadIdx.x;
        const int4* qp = reinterpret_cast<const int4*>(Q + g * 8);
        int4 q0 = qp[0];
        int4 q1 = qp[1];
        float n = NORM[g];
        float s = n * (2.0f / 7.0f);
        int v[8] = {q0.x, q0.y, q0.z, q0.w, q1.x, q1.y, q1.z, q1.w};
        uint32_t h[8];
#pragma unroll
        for (int i = 0; i < 8; i++) {
            float w0 = fmaf((float)(v[i] & 7), s, -n);
            float w1 = fmaf((float)((v[i] >> 3) & 7), s, -n);
            h[i] = h2u(__floats2half2_rn(w0, w1));
        }
        uint4* dst = reinterpret_cast<uint4*>(g_wh + g * 16);
        uint4 o0, o1;
        o0.x = h[0]; o0.y = h[1]; o0.z = h[2]; o0.w = h[3];
        o1.x = h[4]; o1.y = h[5]; o1.z = h[6]; o1.w = h[7];
        dst[0] = o0;
        dst[1] = o1;
    } else {
        size_t i = (size_t)(b - DEQ_BLOCKS) * 256 + threadIdx.x;  // 8 floats each
        float4 v0 = X[2 * i];
        float4 v1 = X[2 * i + 1];
        uint4 o;
        o.x = h2u(__floats2half2_rn(v0.x, v0.y));
        o.y = h2u(__floats2half2_rn(v0.z, v0.w));
        o.z = h2u(__floats2half2_rn(v1.x, v1.y));
        o.w = h2u(__floats2half2_rn(v1.z, v1.w));
        reinterpret_cast<uint4*>(g_xh)[i] = o;
    }
}

// ---------------- kernel 2: TMA + mbarrier pipelined fp16 mma GEMM ----------
// CTA tile 128(M) x 128(N) x 64(K halves), 256 threads = 8 warps in 2(M) x 4(N),
// warp tile 64 x 32, 2 CTAs/SM. 3 stages; per-stage full/empty mbarriers replace
// the lockstep __syncthreads (warps decouple with 2-stage slack). TMA SW128
// swizzle == the verified XOR-16B-chunk scheme, so ldmatrix addressing is
// unchanged from r14.
#define BM 128
#define BN 128
#define BKH 64
#define STAGES 3
#define STAGE_BYTES 32768                        // A 16KB + B 16KB
#define HDR_BYTES 1024
#define SMEM_BYTES (HDR_BYTES + STAGES * STAGE_BYTES)   // 99328
#define NKT (IN_F / BKH)                          // 64
#define NTH 256

__device__ __forceinline__ void ldsm4(uint32_t* r, uint32_t addr) {
    asm volatile("ldmatrix.sync.aligned.m8n8.x4.shared.b16 {%0,%1,%2,%3}, [%4];"
        : "=r"(r[0]), "=r"(r[1]), "=r"(r[2]), "=r"(r[3]) : "r"(addr));
}

__device__ __forceinline__ void mma_f16(float* d, const uint32_t* a, const uint32_t* b) {
    asm volatile(
        "mma.sync.aligned.m16n8k16.row.col.f32.f16.f16.f32 "
        "{%0,%1,%2,%3}, {%4,%5,%6,%7}, {%8,%9}, {%0,%1,%2,%3};"
        : "+f"(d[0]), "+f"(d[1]), "+f"(d[2]), "+f"(d[3])
        : "r"(a[0]), "r"(a[1]), "r"(a[2]), "r"(a[3]),
          "r"(b[0]), "r"(b[1]));
}

__device__ __forceinline__ void mbar_init(uint32_t a, uint32_t cnt) {
    asm volatile("mbarrier.init.shared.b64 [%0], %1;" :: "r"(a), "r"(cnt) : "memory");
}
__device__ __forceinline__ void mbar_expect_tx(uint32_t a, uint32_t bytes) {
    asm volatile("mbarrier.arrive.expect_tx.shared.b64 _, [%0], %1;"
                 :: "r"(a), "r"(bytes) : "memory");
}
__device__ __forceinline__ void mbar_arrive(uint32_t a) {
    asm volatile("mbarrier.arrive.shared.b64 _, [%0];" :: "r"(a) : "memory");
}
__device__ __forceinline__ void mbar_wait(uint32_t a, uint32_t parity) {
    asm volatile(
        "{\n\t.reg .pred P;\n"
        "WL%=:\n\t"
        "mbarrier.try_wait.parity.shared.b64 P, [%0], %1;\n\t"
        "@P bra WD%=;\n\t"
        "bra WL%=;\n"
        "WD%=:\n\t}"
        :: "r"(a), "r"(parity) : "memory");
}
__device__ __forceinline__ void tma2d(uint32_t dst, const void* tmap,
                                      int c0, int c1, uint32_t mbar) {
    asm volatile(
        "cp.async.bulk.tensor.2d.shared::cta.global.tile.mbarrier::complete_tx::bytes "
        "[%0], [%1, {%2, %3}], [%4];"
        :: "r"(dst), "l"(tmap), "r"(c0), "r"(c1), "r"(mbar) : "memory");
}

__global__ __launch_bounds__(NTH, 2)
void gemm_tma_f16(const __grid_constant__ CUtensorMap tmA,
                  const __grid_constant__ CUtensorMap tmB,
                  const float* __restrict__ bias,
                  float* __restrict__ C,
                  int mtiles)
{
    extern __shared__ __align__(1024) char smem[];
    const uint32_t sb = (uint32_t)__cvta_generic_to_shared(smem);
    const int tid  = threadIdx.x;
    const int lane = tid & 31;
    const int warp = tid >> 5;
    const int wm   = warp & 1;          // M dir: 64 rows each
    const int wn   = warp >> 1;         // N dir: 32 cols each

    // barriers: full[s] at sb+16s, empty[s] at sb+16s+8
#define FULLB(s)  (sb + (uint32_t)(s) * 16)
#define EMPTYB(s) (sb + (uint32_t)(s) * 16 + 8)
#define STAGEA(s) (sb + HDR_BYTES + (uint32_t)(s) * STAGE_BYTES)

    // ---- grouped rasterization (GM=8) ----
    const int NT = OUT_F / BN;          // 86
    const int GM = 8;
    int bid   = blockIdx.x;
    int grp   = bid / (GM * NT);
    int first = grp * GM;
    int gsz   = (mtiles - first < GM) ? (mtiles - first) : GM;
    int rem   = bid - grp * GM * NT;
    int mt    = first + rem % gsz;
    int nt    = rem / gsz;
    const int m0 = mt * BM;
    const int n0 = nt * BN;

    // ---- ldmatrix per-lane address components (verified r7..r16; TMA SW128
    //      swizzle is the same chunk^(row&7) pattern) ----
    const int p  = lane >> 3;
    const int rl = lane & 7;
    const int a_cbit = p >> 1;
    const int a_roff = rl + (p & 1) * 8;
    const int b_cbit = p & 1;
    const int b_roff = rl + (p >> 1) * 8;

    uint32_t a_rowb[4], b_rowb[2];
#pragma unroll
    for (int mi = 0; mi < 4; mi++) a_rowb[mi] = (uint32_t)(wm * 64 + mi * 16 + a_roff) * 128;
#pragma unroll
    for (int nj = 0; nj < 2; nj++) b_rowb[nj] = (uint32_t)(wn * 32 + nj * 16 + b_roff) * 128 + 16384;

    uint32_t aswk[4], bswk[4];
#pragma unroll
    for (int ks = 0; ks < 4; ks++) {
        aswk[ks] = (uint32_t)(((2 * ks + a_cbit) ^ rl) << 4);
        bswk[ks] = (uint32_t)(((2 * ks + b_cbit) ^ rl) << 4);
    }

    float acc[4][4][4];
#pragma unroll
    for (int mi = 0; mi < 4; mi++)
#pragma unroll
        for (int ni = 0; ni < 4; ni++)
#pragma unroll
            for (int q = 0; q < 4; q++) acc[mi][ni][q] = 0.0f;

    // ---- init barriers ----
    if (tid == 0) {
#pragma unroll
        for (int s = 0; s < STAGES; s++) {
            mbar_init(FULLB(s), 1);     // 1 expect_tx arrive from producer
            mbar_init(EMPTYB(s), 8);    // 8 warp arrivals from consumers
        }
    }
    __syncthreads();

    uint32_t af[4][4], bf[2][4];

#define LD_FRAGS(ks, base) do {                                                   \
    _Pragma("unroll")                                                             \
    for (int mi = 0; mi < 4; mi++) ldsm4(af[mi], (base) + a_rowb[mi] + aswk[ks]); \
    _Pragma("unroll")                                                             \
    for (int nj = 0; nj < 2; nj++) ldsm4(bf[nj], (base) + b_rowb[nj] + bswk[ks]); \
} while (0)

    // ---- producer prologue: stages 0..1 (tid 0 only) ----
    int ps = 0, pph = 1;                // fresh-barrier wait with parity 1 passes
    if (tid == 0) {
#pragma unroll
        for (int s = 0; s < STAGES - 1; s++) {
            mbar_expect_tx(FULLB(ps), STAGE_BYTES);
            tma2d(STAGEA(ps), &tmA, s * BKH, m0, FULLB(ps));
            tma2d(STAGEA(ps) + 16384, &tmB, s * BKH, n0, FULLB(ps));
            if (++ps == STAGES) { ps = 0; pph ^= 1; }
        }
    }

    int cs = 0, cph = 0;
    for (int t = 0; t < NKT; t++) {
        // producer: issue stage t+2 (tid 0) — waits only on consumer drain
        if (tid == 0 && t + STAGES - 1 < NKT) {
            mbar_wait(EMPTYB(ps), (uint32_t)pph);
            mbar_expect_tx(FULLB(ps), STAGE_BYTES);
            tma2d(STAGEA(ps), &tmA, (t + STAGES - 1) * BKH, m0, FULLB(ps));
            tma2d(STAGEA(ps) + 16384, &tmB, (t + STAGES - 1) * BKH, n0, FULLB(ps));
            if (++ps == STAGES) { ps = 0; pph ^= 1; }
        }

        // consumer: wait stage full, compute, release
        mbar_wait(FULLB(cs), (uint32_t)cph);
        const uint32_t base = STAGEA(cs);
#pragma unroll
        for (int ks = 0; ks < 4; ks++) {
            LD_FRAGS(ks, base);
#pragma unroll
            for (int mi = 0; mi < 4; mi++)
#pragma unroll
                for (int ni = 0; ni < 4; ni++)
                    mma_f16(acc[mi][ni], af[mi], &bf[ni >> 1][(ni & 1) * 2]);
        }
        // MMAs consumed the frags -> smem reads complete; release the stage
        if (lane == 0) mbar_arrive(EMPTYB(cs));
        if (++cs == STAGES) { cs = 0; cph ^= 1; }
    }

    // ---- epilogue: bias + store ----
    const int g = lane >> 2;
    const int tig = lane & 3;
#pragma unroll
    for (int mi = 0; mi < 4; mi++) {
        const int row = m0 + wm * 64 + mi * 16 + g;
        float* c0 = C + (size_t)row * OUT_F;
        float* c1 = C + (size_t)(row + 8) * OUT_F;
#pragma unroll
        for (int ni = 0; ni < 4; ni++) {
            const int col = n0 + wn * 32 + ni * 8 + tig * 2;
            float2 bv = *reinterpret_cast<const float2*>(bias + col);
            float2 o0, o1;
            o0.x = acc[mi][ni][0] + bv.x;
            o0.y = acc[mi][ni][1] + bv.y;
            o1.x = acc[mi][ni][2] + bv.x;
            o1.y = acc[mi][ni][3] + bv.y;
            *reinterpret_cast<float2*>(c0 + col) = o0;
            *reinterpret_cast<float2*>(c1 + col) = o1;
        }
    }
}

// ---------------- host launcher ----------------
typedef CUresult (*PFN_tmapEncode)(
    CUtensorMap*, CUtensorMapDataType, cuuint32_t, void*,
    const cuuint64_t*, const cuuint64_t*, const cuuint32_t*, const cuuint32_t*,
    CUtensorMapInterleave, CUtensorMapSwizzle, CUtensorMapL2promotion,
    CUtensorMapFloatOOBfill);

extern "C" void kernel_launch(void* const* d_in, const int* in_sizes, int n_in,
                              void* d_out, int out_size)
{
    const float* x    = (const float*)d_in[0];
    const int*   q3   = (const int*)  d_in[1];
    const float* nrm  = (const float*)d_in[2];
    const float* bias = (const float*)d_in[3];
    float* out = (float*)d_out;

    const int M = in_sizes[0] / IN_F;            // 8192

    void* wptr = nullptr; cudaGetSymbolAddress(&wptr, g_wh);
    void* xptr = nullptr; cudaGetSymbolAddress(&xptr, g_xh);

    prep_kernel<<<DEQ_BLOCKS + CONV_BLOCKS, 256>>>(
        q3, nrm, reinterpret_cast<const float4*>(x));

    // tensor maps: [K halves, rows], box [64, 128], SW128
    PFN_tmapEncode enc = nullptr;
    cudaDriverEntryPointQueryResult qr;
    cudaGetDriverEntryPointByVersion("cuTensorMapEncodeTiled", (void**)&enc,
                                     12000, cudaEnableDefault, &qr);
    CUtensorMap tmA, tmB;
    {
        cuuint64_t dims[2] = {IN_F, (cuuint64_t)M};
        cuuint64_t strd[1] = {IN_F * sizeof(__half)};
        cuuint32_t box[2]  = {BKH, BM};
        cuuint32_t es[2]   = {1, 1};
        enc(&tmA, CU_TENSOR_MAP_DATA_TYPE_FLOAT16, 2, xptr, dims, strd, box, es,
            CU_TENSOR_MAP_INTERLEAVE_NONE, CU_TENSOR_MAP_SWIZZLE_128B,
            CU_TENSOR_MAP_L2_PROMOTION_L2_128B, CU_TENSOR_MAP_FLOAT_OOB_FILL_NONE);
    }
    {
        cuuint64_t dims[2] = {IN_F, OUT_F};
        cuuint64_t strd[1] = {IN_F * sizeof(__half)};
        cuuint32_t box[2]  = {BKH, BN};
        cuuint32_t es[2]   = {1, 1};
        enc(&tmB, CU_TENSOR_MAP_DATA_TYPE_FLOAT16, 2, wptr, dims, strd, box, es,
            CU_TENSOR_MAP_INTERLEAVE_NONE, CU_TENSOR_MAP_SWIZZLE_128B,
            CU_TENSOR_MAP_L2_PROMOTION_L2_128B, CU_TENSOR_MAP_FLOAT_OOB_FILL_NONE);
    }

    cudaFuncSetAttribute(gemm_tma_f16,
                         cudaFuncAttributeMaxDynamicSharedMemorySize, SMEM_BYTES);
    const int mtiles = M / BM;                   // 64
    const int grid = mtiles * (OUT_F / BN);      // 5504
    gemm_tma_f16<<<grid, NTH, SMEM_BYTES>>>(tmA, tmB, bias, out, mtiles);
}